// round 13
// baseline (speedup 1.0000x reference)
#include <cuda_runtime.h>
#include <cuda_fp16.h>
#include <cstdint>
#include <cstddef>

// Problem constants
#define DIMN 256
#define KTOK 2048
#define BSZ  256
#define NQQ  64     // dedicated qq CTAs (4 b-rows each)

// ---------------- device globals (scratch; no allocs allowed) ----------------
__device__ __align__(16) float   g_qq[BSZ * DIMN];   // query@Wq^T + bq + bref
__device__ __align__(16) __half  g_W16[DIMN * DIMN]; // Wref rounded to fp16
__device__ unsigned int          g_qq_ctr;           // monotonic; replay-safe

// ---------------- helpers ----------------
__device__ __forceinline__ uint32_t smem_u32(const void* p) {
    return (uint32_t)__cvta_generic_to_shared(p);
}

__device__ __forceinline__ uint32_t swz(uint32_t o) {
    return o ^ ((o >> 3) & 0x70);
}

__device__ __forceinline__ uint32_t pack2h(__half a, __half b) {
    __half2 t(a, b);  // a at low half
    return *reinterpret_cast<uint32_t*>(&t);
}

__device__ __forceinline__ float tanha(float x) {
    float y;
    asm("tanh.approx.f32 %0, %1;" : "=f"(y) : "f"(x));
    return y;
}

__device__ __forceinline__ void ldsm4(uint32_t* r, uint32_t addr) {
    asm volatile("ldmatrix.sync.aligned.m8n8.x4.shared.b16 {%0,%1,%2,%3}, [%4];"
                 : "=r"(r[0]), "=r"(r[1]), "=r"(r[2]), "=r"(r[3])
                 : "r"(addr));
}

__device__ __forceinline__ void mma_f16(float* c, const uint32_t* a,
                                        uint32_t b0, uint32_t b1) {
    asm volatile(
        "mma.sync.aligned.m16n8k16.row.col.f32.f16.f16.f32 "
        "{%0,%1,%2,%3}, {%4,%5,%6,%7}, {%8,%9}, {%0,%1,%2,%3};"
        : "+f"(c[0]), "+f"(c[1]), "+f"(c[2]), "+f"(c[3])
        : "r"(a[0]), "r"(a[1]), "r"(a[2]), "r"(a[3]), "r"(b0), "r"(b1));
}

__device__ __forceinline__ void cp_async16(uint32_t dst, const void* src) {
    asm volatile("cp.async.cg.shared.global [%0], [%1], 16;"
                 :: "r"(dst), "l"(src) : "memory");
}

__device__ __forceinline__ void prefetch_l1(const void* p) {
    asm volatile("prefetch.global.L1 [%0];" :: "l"(p));
}

// ---------------- prep kernel ----------------
__global__ void prep_w16(const float* __restrict__ Wref) {
    int i = blockIdx.x * blockDim.x + threadIdx.x;  // 65536 total
    g_W16[i] = __float2half(Wref[i]);
}

// ---------------- main kernel ----------------
// Grid (2112, 2):
//   y==0 && x<64  -> qq CTA (b rows 4x..4x+3), exits early
//   y==1 && x<64  -> exits immediately
//   x>=64         -> main GEMM CTA, token k = x-64, b-half = y
// SMEM (112KB -> 2 CTAs/SM):
//   A chunks 0..3 (fp16, write-once, whole K resident): c*16384, [0, 65536)
//   W ring slot r (r=0,1,2): 65536 + r*16384  (128 d-rows x 128B, fp16)
//   qq CTAs use [0,4096) as qrow scratch; red reuses [0,1024) at the end.
#define SM_W   65536
#define SMEM_TOTAL 114688

__global__ void __launch_bounds__(256, 2) attn_main(const float* __restrict__ enc,
                                                    const float* __restrict__ vvec,
                                                    const float* __restrict__ query,
                                                    const float* __restrict__ Wq,
                                                    const float* __restrict__ bq,
                                                    const float* __restrict__ bref,
                                                    float* __restrict__ out) {
    extern __shared__ char smem[];
    const uint32_t sb = smem_u32(smem);
    const int tid = threadIdx.x;

    // ---- dedicated qq CTAs: 4 b-rows each, Wq read once feeds 4 chains ----
    if (blockIdx.x < NQQ) {
        if (blockIdx.y != 0) return;
        const int bq0 = blockIdx.x * 4;
        float* qrows = (float*)smem;  // 4 x 256 floats
#pragma unroll
        for (int r = 0; r < 4; r++)
            qrows[r * DIMN + tid] = query[(bq0 + r) * DIMN + tid];
        __syncthreads();
        const float4* w  = (const float4*)(Wq + (size_t)tid * DIMN);
        const float4* a0 = (const float4*)(qrows);
        const float4* a1 = (const float4*)(qrows + DIMN);
        const float4* a2 = (const float4*)(qrows + 2 * DIMN);
        const float4* a3 = (const float4*)(qrows + 3 * DIMN);
        float s0 = 0.f, s1 = 0.f, s2 = 0.f, s3 = 0.f;
#pragma unroll 8
        for (int e = 0; e < 64; e++) {
            float4 wv = w[e];
            float4 x0 = a0[e], x1 = a1[e], x2 = a2[e], x3 = a3[e];
            s0 = fmaf(wv.x, x0.x, fmaf(wv.y, x0.y, fmaf(wv.z, x0.z, fmaf(wv.w, x0.w, s0))));
            s1 = fmaf(wv.x, x1.x, fmaf(wv.y, x1.y, fmaf(wv.z, x1.z, fmaf(wv.w, x1.w, s1))));
            s2 = fmaf(wv.x, x2.x, fmaf(wv.y, x2.y, fmaf(wv.z, x2.z, fmaf(wv.w, x2.w, s2))));
            s3 = fmaf(wv.x, x3.x, fmaf(wv.y, x3.y, fmaf(wv.z, x3.z, fmaf(wv.w, x3.w, s3))));
        }
        const float bb = bq[tid] + bref[tid];
        g_qq[(bq0 + 0) * DIMN + tid] = s0 + bb;
        g_qq[(bq0 + 1) * DIMN + tid] = s1 + bb;
        g_qq[(bq0 + 2) * DIMN + tid] = s2 + bb;
        g_qq[(bq0 + 3) * DIMN + tid] = s3 + bb;
        __threadfence();           // writer-side release (64 CTAs only; cheap)
        __syncthreads();
        if (tid == 0) atomicAdd(&g_qq_ctr, 1u);
        return;
    }

    // ---- main GEMM CTA ----
    const int wid = tid >> 5;
    const int lane = tid & 31;
    const int wm = wid & 3;            // M block: rows wm*32 .. +32
    const int wn = wid >> 2;           // N half within pass: cols wn*64 .. +64
    const int k = blockIdx.x - NQQ;
    const int b0 = blockIdx.y * 128;
    const int kb = k * BSZ + b0;

    // per-lane swizzled ldmatrix bases
    const uint32_t a0 = swz((uint32_t)((wm * 32 + (lane & 15)) * 128 + (lane >> 4) * 16));
    const uint32_t a1 = a0 + 2048;  // +16 rows (additive above swizzle bits)
    const uint32_t w_row = (uint32_t)((lane & 7) + ((lane & 16) ? 8 : 0));
    const uint32_t w0s = swz((uint32_t)((wn * 64 + w_row) * 128 + ((lane >> 3) & 1) * 16));

    // W issue for linear stage s (pass s>>2, chunk s&3) into ring slot s%3
    auto issue_W = [&](int s) {
        uint32_t wst = sb + SM_W + (uint32_t)(s % 3) * 16384;
        const __half* src = g_W16 + ((s >> 2) * 128) * DIMN + (s & 3) * 64;
#pragma unroll
        for (int j = 0; j < 4; j++) {
            int gi = j * 256 + tid;           // 1024 granules of 16B
            int d = gi >> 3, seg = gi & 7;
            cp_async16(wst + swz((uint32_t)(d * 128 + seg * 16)),
                       src + d * DIMN + seg * 8);
        }
        asm volatile("cp.async.commit_group;" ::: "memory");
    };

    // A granule helpers: granule gi covers row m=gi>>4, floats f4=(gi&15)*4
    auto ldgA = [&](float4* st, int c, int jbase) {
#pragma unroll
        for (int j = 0; j < 4; j++) {
            int gi = (jbase + j) * 256 + tid;
            int m = gi >> 4, f4 = gi & 15;
            st[j] = *(const float4*)(enc + (size_t)(kb + m) * DIMN + c * 64 + f4 * 4);
        }
    };
    auto stsA = [&](const float4* st, int c, int jbase) {
#pragma unroll
        for (int j = 0; j < 4; j++) {
            int gi = (jbase + j) * 256 + tid;
            int m = gi >> 4, f4 = gi & 15;
            __half h0 = __float2half(st[j].x), h1 = __float2half(st[j].y);
            __half h2 = __float2half(st[j].z), h3 = __float2half(st[j].w);
            uint32_t sw = swz((uint32_t)(m * 128 + f4 * 8));
            *(uint2*)(smem + (size_t)c * 16384 + sw) =
                make_uint2(pack2h(h0, h1), pack2h(h2, h3));
        }
    };

    // ---- prologue: W0, W1 in flight; A chunk 0 loaded cold ----
    issue_W(0);
    issue_W(1);
    {
        float4 st[8];
        ldgA(st, 0, 0);
        ldgA(st + 4, 0, 4);
        stsA(st, 0, 0);
        stsA(st + 4, 0, 4);
    }

    // accumulators: 2 m-tiles x 8 n8-tiles x 4 regs (one 128-col pass at a time)
    float acc[2][8][4];
#pragma unroll
    for (int mt = 0; mt < 2; mt++)
#pragma unroll
        for (int t = 0; t < 8; t++)
#pragma unroll
            for (int j = 0; j < 4; j++) acc[mt][t][j] = 0.0f;

    float u00 = 0.f, u01 = 0.f, u10 = 0.f, u11 = 0.f;

    // epilogue row indices / qq pointers (rows wm*32 + q + {0,8,16,24})
    const int q = lane >> 2;
    const int rbase = b0 + wm * 32 + q;
    const float* qp0 = g_qq + (size_t)rbase * DIMN;
    const float* qp1 = g_qq + (size_t)(rbase + 8) * DIMN;
    const float* qp2 = g_qq + (size_t)(rbase + 16) * DIMN;
    const float* qp3 = g_qq + (size_t)(rbase + 24) * DIMN;
    const int cbase = 2 * (lane & 3);

    for (int s = 0; s < 8; s++) {
        const int c = s & 3;
        const int pe = s >> 2;
        const uint32_t abase = sb + (uint32_t)c * 16384;
        const uint32_t wbase = sb + SM_W + (uint32_t)(s % 3) * 16384;

        // confirm qq publication before its first use (fold at s==3); the spin
        // rides the s==2 sync. No reader fence needed: this CTA never touched
        // g_qq, so no stale L1 lines; syncthreads orders + compiler-bars.
        if (s == 2 && tid == 0) {
            while (atomicAdd(&g_qq_ctr, 0u) < (unsigned)NQQ) __nanosleep(100);
        }

        // W(s) arrived a full chunk ago; W(s+1) may still be in flight
        if (s < 7) {
            asm volatile("cp.async.wait_group 1;" ::: "memory");
        } else {
            asm volatile("cp.async.wait_group 0;" ::: "memory");
        }
        __syncthreads();  // A STS(c) visible; all warps past compute(s-1)
        if (s + 2 < 8) issue_W(s + 2);  // slot (s+2)%3: readers were compute(s-1)

        const bool pf = (s < 3);        // prefetch A chunk c+1 under compute
        float4 st[4];
        if (pf) ldgA(st, c + 1, 0);

        // ---- compute kk = 0,1 (hides group-0 LDG latency) ----
#pragma unroll
        for (int kk = 0; kk < 2; kk++) {
            const uint32_t kx = (uint32_t)(kk * 32);
            uint32_t aF0[4], aF1[4];
            ldsm4(aF0, abase + (a0 ^ kx));
            ldsm4(aF1, abase + (a1 ^ kx));
            const uint32_t wk = w0s ^ kx;
#pragma unroll
            for (int np = 0; np < 4; np++) {
                uint32_t w[4];
                ldsm4(w, wbase + wk + np * 2048);
                mma_f16(acc[0][2 * np],     aF0, w[0], w[1]);
                mma_f16(acc[0][2 * np + 1], aF0, w[2], w[3]);
                mma_f16(acc[1][2 * np],     aF1, w[0], w[1]);
                mma_f16(acc[1][2 * np + 1], aF1, w[2], w[3]);
            }
        }

        if (pf) {
            stsA(st, c + 1, 0);         // group 0 done; store (no reader yet)
            ldgA(st, c + 1, 4);         // group 1 in flight under kk=2,3
        }

        // ---- compute kk = 2,3 ----
#pragma unroll
        for (int kk = 2; kk < 4; kk++) {
            const uint32_t kx = (uint32_t)(kk * 32);
            uint32_t aF0[4], aF1[4];
            ldsm4(aF0, abase + (a0 ^ kx));
            ldsm4(aF1, abase + (a1 ^ kx));
            const uint32_t wk = w0s ^ kx;
#pragma unroll
            for (int np = 0; np < 4; np++) {
                uint32_t w[4];
                ldsm4(w, wbase + wk + np * 2048);
                mma_f16(acc[0][2 * np],     aF0, w[0], w[1]);
                mma_f16(acc[0][2 * np + 1], aF0, w[2], w[3]);
                mma_f16(acc[1][2 * np],     aF1, w[0], w[1]);
                mma_f16(acc[1][2 * np + 1], aF1, w[2], w[3]);
            }
        }

        if (pf) stsA(st, c + 1, 4);

        // prefetch qq lines one iteration before each fold
        if (c == 2) {
            const int cb0 = pe * 128 + wn * 64;
#pragma unroll
            for (int h = 0; h < 2; h++) {
                prefetch_l1(qp0 + cb0 + h * 32);
                prefetch_l1(qp1 + cb0 + h * 32);
                prefetch_l1(qp2 + cb0 + h * 32);
                prefetch_l1(qp3 + cb0 + h * 32);
            }
        }

        // ---- end of a pass: fold this 128-col half into u, reset acc ----
        if (c == 3) {
#pragma unroll
            for (int t = 0; t < 8; t++) {
                int cb = pe * 128 + wn * 64 + t * 8 + cbase;
                float2 vv = *(const float2*)(vvec + cb);
                float2 qa = *(const float2*)(qp0 + cb);
                float2 qb = *(const float2*)(qp1 + cb);
                float2 qc = *(const float2*)(qp2 + cb);
                float2 qd = *(const float2*)(qp3 + cb);
                u00 = fmaf(vv.x, tanha(acc[0][t][0] + qa.x), u00);
                u00 = fmaf(vv.y, tanha(acc[0][t][1] + qa.y), u00);
                u01 = fmaf(vv.x, tanha(acc[0][t][2] + qb.x), u01);
                u01 = fmaf(vv.y, tanha(acc[0][t][3] + qb.y), u01);
                u10 = fmaf(vv.x, tanha(acc[1][t][0] + qc.x), u10);
                u10 = fmaf(vv.y, tanha(acc[1][t][1] + qc.y), u10);
                u11 = fmaf(vv.x, tanha(acc[1][t][2] + qd.x), u11);
                u11 = fmaf(vv.y, tanha(acc[1][t][3] + qd.y), u11);
#pragma unroll
                for (int mt = 0; mt < 2; mt++)
#pragma unroll
                    for (int j = 0; j < 4; j++) acc[mt][t][j] = 0.0f;
            }
        }
    }

    // reduce across the 4 lanes sharing each row
    u00 += __shfl_xor_sync(0xFFFFFFFF, u00, 1);
    u00 += __shfl_xor_sync(0xFFFFFFFF, u00, 2);
    u01 += __shfl_xor_sync(0xFFFFFFFF, u01, 1);
    u01 += __shfl_xor_sync(0xFFFFFFFF, u01, 2);
    u10 += __shfl_xor_sync(0xFFFFFFFF, u10, 1);
    u10 += __shfl_xor_sync(0xFFFFFFFF, u10, 2);
    u11 += __shfl_xor_sync(0xFFFFFFFF, u11, 1);
    u11 += __shfl_xor_sync(0xFFFFFFFF, u11, 2);

    // cross-warp (wn) reduction via smem (A chunks are dead now)
    __syncthreads();
    float* red = (float*)smem;  // [2][128]
    if ((lane & 3) == 0) {
        red[wn * 128 + wm * 32 + q] = u00;
        red[wn * 128 + wm * 32 + 8 + q] = u01;
        red[wn * 128 + wm * 32 + 16 + q] = u10;
        red[wn * 128 + wm * 32 + 24 + q] = u11;
    }
    __syncthreads();
    if (tid < 128) {
        float u = red[tid] + red[128 + tid];
        out[(size_t)(b0 + tid) * KTOK + k] = 10.0f * tanhf(u);
    }
}

// ---------------- launch ----------------
extern "C" void kernel_launch(void* const* d_in, const int* in_sizes, int n_in,
                              void* d_out, int out_size) {
    (void)in_sizes; (void)n_in; (void)out_size;
    const float* enc   = (const float*)d_in[0];
    const float* query = (const float*)d_in[1];
    const float* Wq    = (const float*)d_in[2];
    const float* bq    = (const float*)d_in[3];
    const float* Wref  = (const float*)d_in[4];
    const float* bref  = (const float*)d_in[5];
    const float* v     = (const float*)d_in[6];
    float* out = (float*)d_out;

    prep_w16<<<DIMN * DIMN / 256, 256>>>(Wref);

    cudaFuncSetAttribute(attn_main, cudaFuncAttributeMaxDynamicSharedMemorySize,
                         SMEM_TOTAL);
    dim3 grid(KTOK + NQQ, 2);
    attn_main<<<grid, 256, SMEM_TOTAL>>>(enc, v, query, Wq, bq, bref, out);
}

// round 14
// speedup vs baseline: 1.0977x; 1.0977x over previous
#include <cuda_runtime.h>
#include <cuda_fp16.h>
#include <cstdint>
#include <cstddef>

// Problem constants
#define DIMN 256
#define KTOK 2048
#define BSZ  256

// ---------------- device globals (scratch; no allocs allowed) ----------------
__device__ __align__(16) float   g_qq[BSZ * DIMN];   // query@Wq^T + bq + bref
__device__ __align__(16) __half  g_W16[DIMN * DIMN]; // Wref rounded to fp16

// ---------------- helpers ----------------
__device__ __forceinline__ uint32_t smem_u32(const void* p) {
    return (uint32_t)__cvta_generic_to_shared(p);
}

__device__ __forceinline__ uint32_t swz(uint32_t o) {
    return o ^ ((o >> 3) & 0x70);
}

__device__ __forceinline__ uint32_t pack2h(__half a, __half b) {
    __half2 t(a, b);  // a at low half
    return *reinterpret_cast<uint32_t*>(&t);
}

__device__ __forceinline__ float tanha(float x) {
    float y;
    asm("tanh.approx.f32 %0, %1;" : "=f"(y) : "f"(x));
    return y;
}

__device__ __forceinline__ void ldsm4(uint32_t* r, uint32_t addr) {
    asm volatile("ldmatrix.sync.aligned.m8n8.x4.shared.b16 {%0,%1,%2,%3}, [%4];"
                 : "=r"(r[0]), "=r"(r[1]), "=r"(r[2]), "=r"(r[3])
                 : "r"(addr));
}

__device__ __forceinline__ void mma_f16(float* c, const uint32_t* a,
                                        uint32_t b0, uint32_t b1) {
    asm volatile(
        "mma.sync.aligned.m16n8k16.row.col.f32.f16.f16.f32 "
        "{%0,%1,%2,%3}, {%4,%5,%6,%7}, {%8,%9}, {%0,%1,%2,%3};"
        : "+f"(c[0]), "+f"(c[1]), "+f"(c[2]), "+f"(c[3])
        : "r"(a[0]), "r"(a[1]), "r"(a[2]), "r"(a[3]), "r"(b0), "r"(b1));
}

__device__ __forceinline__ void cp_async16(uint32_t dst, const void* src) {
    asm volatile("cp.async.cg.shared.global [%0], [%1], 16;"
                 :: "r"(dst), "l"(src) : "memory");
}

__device__ __forceinline__ void prefetch_l1(const void* p) {
    asm volatile("prefetch.global.L1 [%0];" :: "l"(p));
}

// ---------------- merged prep kernel ----------------
// Grid 96: CTAs 0..63 -> qq (4 b-rows each, 4x Wq reuse + 4-way ILP);
//          CTAs 64..95 -> W16 conversion (2048 elements each).
__global__ void prep_all(const float* __restrict__ query,
                         const float* __restrict__ Wq,
                         const float* __restrict__ bq,
                         const float* __restrict__ bref,
                         const float* __restrict__ Wref) {
    const int tid = threadIdx.x;
    if (blockIdx.x >= 64) {
        int i = (blockIdx.x - 64) * 2048 + tid;
#pragma unroll
        for (int j = 0; j < 8; j++)
            g_W16[i + j * 256] = __float2half(Wref[i + j * 256]);
        return;
    }
    __shared__ __align__(16) float qrows[4 * DIMN];
    const int bq0 = blockIdx.x * 4;
#pragma unroll
    for (int r = 0; r < 4; r++)
        qrows[r * DIMN + tid] = query[(bq0 + r) * DIMN + tid];
    __syncthreads();
    const float4* w  = (const float4*)(Wq + (size_t)tid * DIMN);
    const float4* a0 = (const float4*)(qrows);
    const float4* a1 = (const float4*)(qrows + DIMN);
    const float4* a2 = (const float4*)(qrows + 2 * DIMN);
    const float4* a3 = (const float4*)(qrows + 3 * DIMN);
    float s0 = 0.f, s1 = 0.f, s2 = 0.f, s3 = 0.f;
#pragma unroll 8
    for (int e = 0; e < 64; e++) {
        float4 wv = w[e];
        float4 x0 = a0[e], x1 = a1[e], x2 = a2[e], x3 = a3[e];
        s0 = fmaf(wv.x, x0.x, fmaf(wv.y, x0.y, fmaf(wv.z, x0.z, fmaf(wv.w, x0.w, s0))));
        s1 = fmaf(wv.x, x1.x, fmaf(wv.y, x1.y, fmaf(wv.z, x1.z, fmaf(wv.w, x1.w, s1))));
        s2 = fmaf(wv.x, x2.x, fmaf(wv.y, x2.y, fmaf(wv.z, x2.z, fmaf(wv.w, x2.w, s2))));
        s3 = fmaf(wv.x, x3.x, fmaf(wv.y, x3.y, fmaf(wv.z, x3.z, fmaf(wv.w, x3.w, s3))));
    }
    const float bb = bq[tid] + bref[tid];
    g_qq[(bq0 + 0) * DIMN + tid] = s0 + bb;
    g_qq[(bq0 + 1) * DIMN + tid] = s1 + bb;
    g_qq[(bq0 + 2) * DIMN + tid] = s2 + bb;
    g_qq[(bq0 + 3) * DIMN + tid] = s3 + bb;
}

// ---------------- main kernel ----------------
// Grid (2048, 2): token k = blockIdx.x, b-half = blockIdx.y.
// SMEM (97KB -> 2 CTAs/SM):
//   A chunks 0..3 (fp16, write-once, whole K resident): c*16384, [0, 65536)
//   W stage p (p=0,1): 65536 + p*16384  (128 d-rows x 128B, fp16)
//   v: 98304 (1KB).  red reuses [0,1024) at the end.
#define SM_W   65536
#define SM_V   98304
#define SMEM_TOTAL 99328

__global__ void __launch_bounds__(256, 2) attn_main(const float* __restrict__ enc,
                                                    const float* __restrict__ vvec,
                                                    float* __restrict__ out) {
    extern __shared__ char smem[];
    const uint32_t sb = smem_u32(smem);
    const int tid = threadIdx.x;
    const int wid = tid >> 5;
    const int lane = tid & 31;
    const int wm = wid & 3;            // M block: rows wm*32 .. +32
    const int wn = wid >> 2;           // N half within pass: cols wn*64 .. +64
    const int k = blockIdx.x;
    const int b0 = blockIdx.y * 128;
    const int kb = k * BSZ + b0;

    float* v_s = (float*)(smem + SM_V);
    v_s[tid] = vvec[tid];

    // per-lane swizzled ldmatrix bases
    const uint32_t a0 = swz((uint32_t)((wm * 32 + (lane & 15)) * 128 + (lane >> 4) * 16));
    const uint32_t a1 = a0 + 2048;  // +16 rows (additive above swizzle bits)
    const uint32_t w_row = (uint32_t)((lane & 7) + ((lane & 16) ? 8 : 0));
    const uint32_t w0s = swz((uint32_t)((wn * 64 + w_row) * 128 + ((lane >> 3) & 1) * 16));

    // W stage issue: stage s; d-rows (s>>2)*128+[0,128), k-cols (s&3)*64+[0,64)
    auto issue_W = [&](int s) {
        uint32_t wst = sb + SM_W + (uint32_t)(s & 1) * 16384;
        const __half* src = g_W16 + ((s >> 2) * 128) * DIMN + (s & 3) * 64;
#pragma unroll
        for (int j = 0; j < 4; j++) {
            int gi = j * 256 + tid;           // 1024 granules of 16B
            int d = gi >> 3, seg = gi & 7;
            cp_async16(wst + swz((uint32_t)(d * 128 + seg * 16)),
                       src + d * DIMN + seg * 8);
        }
        asm volatile("cp.async.commit_group;" ::: "memory");
    };

    // accumulators: 2 m-tiles x 8 n8-tiles x 4 regs (one 128-col pass at a time)
    float acc[2][8][4];
#pragma unroll
    for (int mt = 0; mt < 2; mt++)
#pragma unroll
        for (int t = 0; t < 8; t++)
#pragma unroll
            for (int j = 0; j < 4; j++) acc[mt][t][j] = 0.0f;

    float u00 = 0.f, u01 = 0.f, u10 = 0.f, u11 = 0.f;

    // epilogue row indices / qq pointers (rows wm*32 + q + {0,8,16,24})
    const int q = lane >> 2;
    const int rbase = b0 + wm * 32 + q;
    const float* qp0 = g_qq + (size_t)rbase * DIMN;
    const float* qp1 = g_qq + (size_t)(rbase + 8) * DIMN;
    const float* qp2 = g_qq + (size_t)(rbase + 16) * DIMN;
    const float* qp3 = g_qq + (size_t)(rbase + 24) * DIMN;
    const int cbase = 2 * (lane & 3);

    issue_W(0);

    for (int s = 0; s < 8; s++) {
        const int c = s & 3;
        const int pe = s >> 2;
        const uint32_t abase = sb + (uint32_t)c * 16384;
        const uint32_t wbase = sb + SM_W + (uint32_t)(s & 1) * 16384;

        if (s < 4) {
            // pass 0: load A chunk c from gmem, convert fp16, STS (write-once)
            float4 st[8];
#pragma unroll
            for (int j = 0; j < 8; j++) {
                int gi = j * 256 + tid;
                int m = gi >> 4, f4 = gi & 15;
                st[j] = *(const float4*)(enc + (size_t)(kb + m) * DIMN +
                                         c * 64 + f4 * 4);
            }
#pragma unroll
            for (int j = 0; j < 8; j++) {
                int gi = j * 256 + tid;
                int m = gi >> 4, f4 = gi & 15;
                __half h0 = __float2half(st[j].x), h1 = __float2half(st[j].y);
                __half h2 = __float2half(st[j].z), h3 = __float2half(st[j].w);
                uint32_t sw = swz((uint32_t)(m * 128 + f4 * 8));
                *(uint2*)(smem + (size_t)c * 16384 + sw) =
                    make_uint2(pack2h(h0, h1), pack2h(h2, h3));
            }
        }

        // prefetch qq lines for the upcoming pass-boundary epilogue
        if (c == 3) {
            const int cb0 = pe * 128 + wn * 64;
#pragma unroll
            for (int h = 0; h < 2; h++) {
                prefetch_l1(qp0 + cb0 + h * 32);
                prefetch_l1(qp1 + cb0 + h * 32);
                prefetch_l1(qp2 + cb0 + h * 32);
                prefetch_l1(qp3 + cb0 + h * 32);
            }
        }

        // W(s) arrived (issued a full compute phase ago)
        asm volatile("cp.async.wait_group 0;" ::: "memory");
        __syncthreads();  // A STS visible; all warps done with compute(s-1)
        if (s < 7) issue_W(s + 1);  // other W buffer free after sync

        // ---- compute chunk: 4 kk x 4 np x 4 MMA ----
#pragma unroll
        for (int kk = 0; kk < 4; kk++) {
            const uint32_t kx = (uint32_t)(kk * 32);
            uint32_t aF0[4], aF1[4];
            ldsm4(aF0, abase + (a0 ^ kx));
            ldsm4(aF1, abase + (a1 ^ kx));
            const uint32_t wk = w0s ^ kx;
#pragma unroll
            for (int np = 0; np < 4; np++) {
                uint32_t w[4];
                ldsm4(w, wbase + wk + np * 2048);
                mma_f16(acc[0][2 * np],     aF0, w[0], w[1]);
                mma_f16(acc[0][2 * np + 1], aF0, w[2], w[3]);
                mma_f16(acc[1][2 * np],     aF1, w[0], w[1]);
                mma_f16(acc[1][2 * np + 1], aF1, w[2], w[3]);
            }
        }

        // ---- end of a pass: fold this 128-col half into u, reset acc ----
        if (c == 3) {
#pragma unroll
            for (int t = 0; t < 8; t++) {
                int cb = pe * 128 + wn * 64 + t * 8 + cbase;
                float2 vv = *(const float2*)(v_s + cb);
                float2 qa = *(const float2*)(qp0 + cb);
                float2 qb = *(const float2*)(qp1 + cb);
                float2 qc = *(const float2*)(qp2 + cb);
                float2 qd = *(const float2*)(qp3 + cb);
                u00 = fmaf(vv.x, tanha(acc[0][t][0] + qa.x), u00);
                u00 = fmaf(vv.y, tanha(acc[0][t][1] + qa.y), u00);
                u01 = fmaf(vv.x, tanha(acc[0][t][2] + qb.x), u01);
                u01 = fmaf(vv.y, tanha(acc[0][t][3] + qb.y), u01);
                u10 = fmaf(vv.x, tanha(acc[1][t][0] + qc.x), u10);
                u10 = fmaf(vv.y, tanha(acc[1][t][1] + qc.y), u10);
                u11 = fmaf(vv.x, tanha(acc[1][t][2] + qd.x), u11);
                u11 = fmaf(vv.y, tanha(acc[1][t][3] + qd.y), u11);
#pragma unroll
                for (int mt = 0; mt < 2; mt++)
#pragma unroll
                    for (int j = 0; j < 4; j++) acc[mt][t][j] = 0.0f;
            }
        }
    }

    // reduce across the 4 lanes sharing each row
    u00 += __shfl_xor_sync(0xFFFFFFFF, u00, 1);
    u00 += __shfl_xor_sync(0xFFFFFFFF, u00, 2);
    u01 += __shfl_xor_sync(0xFFFFFFFF, u01, 1);
    u01 += __shfl_xor_sync(0xFFFFFFFF, u01, 2);
    u10 += __shfl_xor_sync(0xFFFFFFFF, u10, 1);
    u10 += __shfl_xor_sync(0xFFFFFFFF, u10, 2);
    u11 += __shfl_xor_sync(0xFFFFFFFF, u11, 1);
    u11 += __shfl_xor_sync(0xFFFFFFFF, u11, 2);

    // cross-warp (wn) reduction via smem (A chunks are dead now)
    __syncthreads();
    float* red = (float*)smem;  // [2][128]
    if ((lane & 3) == 0) {
        red[wn * 128 + wm * 32 + q] = u00;
        red[wn * 128 + wm * 32 + 8 + q] = u01;
        red[wn * 128 + wm * 32 + 16 + q] = u10;
        red[wn * 128 + wm * 32 + 24 + q] = u11;
    }
    __syncthreads();
    if (tid < 128) {
        float u = red[tid] + red[128 + tid];
        out[(size_t)(b0 + tid) * KTOK + k] = 10.0f * tanhf(u);
    }
}

// ---------------- launch ----------------
extern "C" void kernel_launch(void* const* d_in, const int* in_sizes, int n_in,
                              void* d_out, int out_size) {
    (void)in_sizes; (void)n_in; (void)out_size;
    const float* enc   = (const float*)d_in[0];
    const float* query = (const float*)d_in[1];
    const float* Wq    = (const float*)d_in[2];
    const float* bq    = (const float*)d_in[3];
    const float* Wref  = (const float*)d_in[4];
    const float* bref  = (const float*)d_in[5];
    const float* v     = (const float*)d_in[6];
    float* out = (float*)d_out;

    prep_all<<<96, 256>>>(query, Wq, bq, bref, Wref);

    cudaFuncSetAttribute(attn_main, cudaFuncAttributeMaxDynamicSharedMemorySize,
                         SMEM_TOTAL);
    dim3 grid(KTOK, 2);
    attn_main<<<grid, 256, SMEM_TOTAL>>>(enc, v, out);
}